// round 2
// baseline (speedup 1.0000x reference)
#include <cuda_runtime.h>
#include <cstdint>

#define C_HID   1024
#define NHEADS  16
#define HD      64
#define NBATCH  2
#define SEQ     4096
#define MTOT    (NBATCH * SEQ)          // 8192
#define SCALE   0.125f                  // HD^-0.5

// Scratch (device globals: no allocations allowed)
__device__ float g_q[(size_t)NBATCH * NHEADS * SEQ * HD];    // [bh][n][d]
__device__ float g_k[(size_t)NBATCH * NHEADS * SEQ * HD];
__device__ float g_v[(size_t)NBATCH * NHEADS * SEQ * HD];
__device__ float g_att[(size_t)MTOT * C_HID];                // [b][n][h*64+d]

// ---------------------------------------------------------------------------
// Kernel 1: qkv = x @ qkv_w^T + qkv_b, scattered into head-major Q/K/V.
// BM=BN=64, BK=16, 256 threads, 4x4 register tile per thread.
// ---------------------------------------------------------------------------
__global__ __launch_bounds__(256) void qkv_gemm_kernel(
    const float* __restrict__ x, const float* __restrict__ w,
    const float* __restrict__ bias)
{
    __shared__ float As[16 * 64];   // As[k][m]
    __shared__ float Bs[16 * 64];   // Bs[k][n]
    const int m0 = blockIdx.x * 64;
    const int c0 = blockIdx.y * 64;
    const int t  = threadIdx.x;
    const int tm = t >> 4, tn = t & 15;
    const int arow = t >> 2, akv = t & 3;

    float acc[4][4];
#pragma unroll
    for (int i = 0; i < 4; i++)
#pragma unroll
        for (int j = 0; j < 4; j++) acc[i][j] = 0.f;

    const float* aptr = x + (size_t)(m0 + arow) * C_HID + akv * 4;
    const float* bptr = w + (size_t)(c0 + arow) * C_HID + akv * 4;

    for (int k0 = 0; k0 < C_HID; k0 += 16) {
        float4 av = *(const float4*)(aptr + k0);
        float4 bv = *(const float4*)(bptr + k0);
        __syncthreads();
        As[(akv * 4 + 0) * 64 + arow] = av.x;
        As[(akv * 4 + 1) * 64 + arow] = av.y;
        As[(akv * 4 + 2) * 64 + arow] = av.z;
        As[(akv * 4 + 3) * 64 + arow] = av.w;
        Bs[(akv * 4 + 0) * 64 + arow] = bv.x;
        Bs[(akv * 4 + 1) * 64 + arow] = bv.y;
        Bs[(akv * 4 + 2) * 64 + arow] = bv.z;
        Bs[(akv * 4 + 3) * 64 + arow] = bv.w;
        __syncthreads();
#pragma unroll
        for (int kk = 0; kk < 16; kk++) {
            float af[4], bf[4];
            *(float4*)af = *(const float4*)&As[kk * 64 + tm * 4];
            *(float4*)bf = *(const float4*)&Bs[kk * 64 + tn * 4];
#pragma unroll
            for (int i = 0; i < 4; i++)
#pragma unroll
                for (int j = 0; j < 4; j++) acc[i][j] += af[i] * bf[j];
        }
    }

    // Epilogue: c0 is 64-aligned so the whole block belongs to one (which, head)
    const int which = c0 / C_HID;                 // 0=q 1=k 2=v
    const int h     = (c0 % C_HID) / HD;
    float* dst = (which == 0) ? g_q : ((which == 1) ? g_k : g_v);

    float bi[4];
#pragma unroll
    for (int j = 0; j < 4; j++) bi[j] = bias[c0 + tn * 4 + j];

#pragma unroll
    for (int i = 0; i < 4; i++) {
        int m = m0 + tm * 4 + i;
        int b = m / SEQ, n = m % SEQ;
        float4 v;
        v.x = acc[i][0] + bi[0];
        v.y = acc[i][1] + bi[1];
        v.z = acc[i][2] + bi[2];
        v.w = acc[i][3] + bi[3];
        *(float4*)&dst[(((size_t)b * NHEADS + h) * SEQ + n) * HD + tn * 4] = v;
    }
}

// ---------------------------------------------------------------------------
// Kernel 2: flash attention, fp32. Block = (64 queries) x (one bh).
// 128 threads: tm in [0,8) owns 8 query rows, tn in [0,16) owns 4 cols.
// Online softmax kept in registers; row reductions via 16-lane shuffles.
// Smem: Qt[d][m] (pre-scaled), KP = Kt[d][n] unioned with P[m][k], Vs[k][d].
// ---------------------------------------------------------------------------
__global__ __launch_bounds__(128) void attn_kernel()
{
    extern __shared__ float sm[];
    float* Qt = sm;           // 4096 floats
    float* KP = sm + 4096;    // 4096 floats (K^T, then P)
    float* Vs = sm + 8192;    // 4096 floats

    const int bh = blockIdx.y;
    const int m0 = blockIdx.x * 64;
    const float* Qg = g_q + (size_t)bh * SEQ * HD + (size_t)m0 * HD;
    const float* Kg = g_k + (size_t)bh * SEQ * HD;
    const float* Vg = g_v + (size_t)bh * SEQ * HD;

    const int t  = threadIdx.x;
    const int tm = t >> 4, tn = t & 15;

    // Load Q transposed (Qt[d][m]) with scale folded in.
#pragma unroll
    for (int i = 0; i < 8; i++) {
        int e  = i * 128 + t;
        int mm = e & 63, dv = e >> 6;
        float4 q = *(const float4*)&Qg[(size_t)mm * HD + dv * 4];
        Qt[(dv * 4 + 0) * 64 + mm] = q.x * SCALE;
        Qt[(dv * 4 + 1) * 64 + mm] = q.y * SCALE;
        Qt[(dv * 4 + 2) * 64 + mm] = q.z * SCALE;
        Qt[(dv * 4 + 3) * 64 + mm] = q.w * SCALE;
    }

    float m_run[8], l_run[8], o[8][4];
#pragma unroll
    for (int i = 0; i < 8; i++) {
        m_run[i] = -1e30f;
        l_run[i] = 0.f;
#pragma unroll
        for (int j = 0; j < 4; j++) o[i][j] = 0.f;
    }

    for (int n0 = 0; n0 < SEQ; n0 += 64) {
        __syncthreads();   // previous PV done reading KP/Vs
        // K tile, transposed into KP[d][n]
#pragma unroll
        for (int i = 0; i < 8; i++) {
            int e  = i * 128 + t;
            int nn = e & 63, dv = e >> 6;
            float4 kv = *(const float4*)&Kg[(size_t)(n0 + nn) * HD + dv * 4];
            KP[(dv * 4 + 0) * 64 + nn] = kv.x;
            KP[(dv * 4 + 1) * 64 + nn] = kv.y;
            KP[(dv * 4 + 2) * 64 + nn] = kv.z;
            KP[(dv * 4 + 3) * 64 + nn] = kv.w;
        }
        // V tile, natural layout Vs[k][d]
#pragma unroll
        for (int i = 0; i < 8; i++) {
            int e  = i * 128 + t;
            int nn = e >> 4, dv = e & 15;
            *(float4*)&Vs[nn * 64 + dv * 4] =
                *(const float4*)&Vg[(size_t)(n0 + nn) * HD + dv * 4];
        }
        __syncthreads();

        // S = (Q*scale) K^T   -> s[8][4] in registers
        float s[8][4];
#pragma unroll
        for (int i = 0; i < 8; i++)
#pragma unroll
            for (int j = 0; j < 4; j++) s[i][j] = 0.f;

        for (int d = 0; d < 64; d++) {
            float qa[8], kb[4];
            *(float4*)(qa)     = *(const float4*)&Qt[d * 64 + tm * 8];
            *(float4*)(qa + 4) = *(const float4*)&Qt[d * 64 + tm * 8 + 4];
            *(float4*)(kb)     = *(const float4*)&KP[d * 64 + tn * 4];
#pragma unroll
            for (int i = 0; i < 8; i++)
#pragma unroll
                for (int j = 0; j < 4; j++) s[i][j] += qa[i] * kb[j];
        }
        __syncthreads();   // everyone done reading KP as K^T

        // Online softmax in registers (row = 16-lane group)
        float alpha[8];
#pragma unroll
        for (int i = 0; i < 8; i++) {
            float mx = fmaxf(fmaxf(s[i][0], s[i][1]), fmaxf(s[i][2], s[i][3]));
            mx = fmaxf(mx, __shfl_xor_sync(0xffffffffu, mx, 8));
            mx = fmaxf(mx, __shfl_xor_sync(0xffffffffu, mx, 4));
            mx = fmaxf(mx, __shfl_xor_sync(0xffffffffu, mx, 2));
            mx = fmaxf(mx, __shfl_xor_sync(0xffffffffu, mx, 1));
            float mnew = fmaxf(m_run[i], mx);
            alpha[i] = __expf(m_run[i] - mnew);
            m_run[i] = mnew;
            float sum = 0.f;
#pragma unroll
            for (int j = 0; j < 4; j++) {
                float p = __expf(s[i][j] - mnew);
                s[i][j] = p;
                sum += p;
            }
            sum += __shfl_xor_sync(0xffffffffu, sum, 8);
            sum += __shfl_xor_sync(0xffffffffu, sum, 4);
            sum += __shfl_xor_sync(0xffffffffu, sum, 2);
            sum += __shfl_xor_sync(0xffffffffu, sum, 1);
            l_run[i] = l_run[i] * alpha[i] + sum;
        }

        // Publish P (reuses KP)
#pragma unroll
        for (int i = 0; i < 8; i++)
            *(float4*)&KP[(tm * 8 + i) * 64 + tn * 4] =
                make_float4(s[i][0], s[i][1], s[i][2], s[i][3]);
        __syncthreads();

        // O = O*alpha + P @ V
#pragma unroll
        for (int i = 0; i < 8; i++) {
            o[i][0] *= alpha[i]; o[i][1] *= alpha[i];
            o[i][2] *= alpha[i]; o[i][3] *= alpha[i];
        }
        for (int k0 = 0; k0 < 64; k0 += 4) {
            float pk[8][4];
#pragma unroll
            for (int i = 0; i < 8; i++)
                *(float4*)pk[i] = *(const float4*)&KP[(tm * 8 + i) * 64 + k0];
#pragma unroll
            for (int kk = 0; kk < 4; kk++) {
                float vb[4];
                *(float4*)vb = *(const float4*)&Vs[(k0 + kk) * 64 + tn * 4];
#pragma unroll
                for (int i = 0; i < 8; i++)
#pragma unroll
                    for (int j = 0; j < 4; j++) o[i][j] += pk[i][kk] * vb[j];
            }
        }
    }

    // Epilogue: O/l -> g_att in [b][n][h*64+d] layout
    const int b = bh / NHEADS, h = bh % NHEADS;
#pragma unroll
    for (int i = 0; i < 8; i++) {
        float inv = 1.f / l_run[i];
        int n = m0 + tm * 8 + i;
        float4 v = make_float4(o[i][0] * inv, o[i][1] * inv,
                               o[i][2] * inv, o[i][3] * inv);
        *(float4*)&g_att[(((size_t)b * SEQ + n) * NHEADS + h) * HD + tn * 4] = v;
    }
}

// ---------------------------------------------------------------------------
// Kernel 3: out = g_att @ out_w^T + out_b
// ---------------------------------------------------------------------------
__global__ __launch_bounds__(256) void out_gemm_kernel(
    const float* __restrict__ w, const float* __restrict__ bias,
    float* __restrict__ out)
{
    __shared__ float As[16 * 64];
    __shared__ float Bs[16 * 64];
    const int m0 = blockIdx.x * 64;
    const int c0 = blockIdx.y * 64;
    const int t  = threadIdx.x;
    const int tm = t >> 4, tn = t & 15;
    const int arow = t >> 2, akv = t & 3;

    float acc[4][4];
#pragma unroll
    for (int i = 0; i < 4; i++)
#pragma unroll
        for (int j = 0; j < 4; j++) acc[i][j] = 0.f;

    const float* aptr = g_att + (size_t)(m0 + arow) * C_HID + akv * 4;
    const float* bptr = w + (size_t)(c0 + arow) * C_HID + akv * 4;

    for (int k0 = 0; k0 < C_HID; k0 += 16) {
        float4 av = *(const float4*)(aptr + k0);
        float4 bv = *(const float4*)(bptr + k0);
        __syncthreads();
        As[(akv * 4 + 0) * 64 + arow] = av.x;
        As[(akv * 4 + 1) * 64 + arow] = av.y;
        As[(akv * 4 + 2) * 64 + arow] = av.z;
        As[(akv * 4 + 3) * 64 + arow] = av.w;
        Bs[(akv * 4 + 0) * 64 + arow] = bv.x;
        Bs[(akv * 4 + 1) * 64 + arow] = bv.y;
        Bs[(akv * 4 + 2) * 64 + arow] = bv.z;
        Bs[(akv * 4 + 3) * 64 + arow] = bv.w;
        __syncthreads();
#pragma unroll
        for (int kk = 0; kk < 16; kk++) {
            float af[4], bf[4];
            *(float4*)af = *(const float4*)&As[kk * 64 + tm * 4];
            *(float4*)bf = *(const float4*)&Bs[kk * 64 + tn * 4];
#pragma unroll
            for (int i = 0; i < 4; i++)
#pragma unroll
                for (int j = 0; j < 4; j++) acc[i][j] += af[i] * bf[j];
        }
    }

    float bi[4];
#pragma unroll
    for (int j = 0; j < 4; j++) bi[j] = bias[c0 + tn * 4 + j];

#pragma unroll
    for (int i = 0; i < 4; i++) {
        int m = m0 + tm * 4 + i;
        float4 v;
        v.x = acc[i][0] + bi[0];
        v.y = acc[i][1] + bi[1];
        v.z = acc[i][2] + bi[2];
        v.w = acc[i][3] + bi[3];
        *(float4*)&out[(size_t)m * C_HID + c0 + tn * 4] = v;
    }
}

// ---------------------------------------------------------------------------
extern "C" void kernel_launch(void* const* d_in, const int* in_sizes, int n_in,
                              void* d_out, int out_size)
{
    const float* x     = (const float*)d_in[0];
    const float* qkv_w = (const float*)d_in[1];
    const float* qkv_b = (const float*)d_in[2];
    const float* out_w = (const float*)d_in[3];
    const float* out_b = (const float*)d_in[4];
    float* outp = (float*)d_out;

    qkv_gemm_kernel<<<dim3(MTOT / 64, 3 * C_HID / 64), 256>>>(x, qkv_w, qkv_b);
    attn_kernel<<<dim3(SEQ / 64, NBATCH * NHEADS), 128, 49152>>>();
    out_gemm_kernel<<<dim3(MTOT / 64, C_HID / 64), 256>>>(out_w, out_b, outp);
}